// round 16
// baseline (speedup 1.0000x reference)
#include <cuda_runtime.h>
#include <cuda_fp16.h>
#include <cstdint>
#include <cstddef>

// ---------------- problem constants ----------------
#define B_TOTAL 131072
#define D_INPUT 385
#define D_H     192
#define NQ      1000
#define NHEADS  2000
#define NC      16

#define KPAD1   448            // 7 chunks of 64
#define NCH1    7
#define NCH2    3
#define PA      72             // smem pitch (halves); 144B row stride -> LDSM banks 4r, conflict-free
#define THR     384            // 12 warps

// ---------------- scratch (device globals: allocation-free) ----------------
__device__ uint32_t g_feat16[(size_t)B_TOTAL * 96];  // trunk output fp16, 50 MB
__device__ __half   g_W1h[D_H * KPAD1];              // W1^T fp16 [n][448], zero-padded
__device__ __half   g_W2h[D_H * D_H];                // W2^T fp16 [n][192]
__device__ int      g_cnt[NHEADS];                   // zero-init; scan re-zeroes each run
__device__ int      g_off[NHEADS + 1];
__device__ int      g_rank[B_TOTAL];
__device__ int      g_order[B_TOTAL];

// ---------------- PTX helpers ----------------
#define CP16(dst, src) \
    asm volatile("cp.async.cg.shared.global [%0], [%1], 16;" \
                 :: "r"(dst), "l"(__cvta_generic_to_global((const void*)(src))))
#define CP_COMMIT() asm volatile("cp.async.commit_group;" ::: "memory")
#define CP_WAIT0()  asm volatile("cp.async.wait_group 0;" ::: "memory")
#define CP_WAIT1()  asm volatile("cp.async.wait_group 1;" ::: "memory")

__device__ __forceinline__ void ldsm4(uint32_t r[4], uint32_t addr) {
    asm volatile("ldmatrix.sync.aligned.m8n8.x4.shared.b16 {%0,%1,%2,%3}, [%4];"
        : "=r"(r[0]), "=r"(r[1]), "=r"(r[2]), "=r"(r[3]) : "r"(addr));
}

__device__ __forceinline__ void mma16(float c[4], uint32_t a0, uint32_t a1,
                                      uint32_t a2, uint32_t a3, uint32_t b0, uint32_t b1) {
    asm volatile(
        "mma.sync.aligned.m16n8k16.row.col.f32.f16.f16.f32 "
        "{%0,%1,%2,%3}, {%4,%5,%6,%7}, {%8,%9}, {%0,%1,%2,%3};\n"
        : "+f"(c[0]), "+f"(c[1]), "+f"(c[2]), "+f"(c[3])
        : "r"(a0), "r"(a1), "r"(a2), "r"(a3), "r"(b0), "r"(b1));
}

// ---------------- prep + hist fused: weight conversion | histogram+rank ----------------
#define T1SZ (D_H * KPAD1)                 // 86016
#define T2SZ (D_H * D_H)                   // 36864
#define PH_TOTAL (T1SZ + T2SZ + B_TOTAL)   // 253952

__global__ void prep_hist_kernel(const float* __restrict__ W1, const float* __restrict__ W2,
                                 const int* __restrict__ qid, const int* __restrict__ cor) {
    int i = blockIdx.x * blockDim.x + threadIdx.x;
    if (i < T1SZ) {
        int n = i / KPAD1, k = i - n * KPAD1;
        float v = (k < D_INPUT) ? W1[(size_t)k * D_H + n] : 0.f;
        g_W1h[i] = __float2half_rn(v);
    } else if (i < T1SZ + T2SZ) {
        int j = i - T1SZ;
        int n = j / D_H, k = j - n * D_H;
        g_W2h[j] = __float2half_rn(W2[(size_t)k * D_H + n]);
    } else {
        int b = i - (T1SZ + T2SZ);
        if (b < B_TOTAL) {
            int h = qid[b] + cor[b] * NQ;
            g_rank[b] = atomicAdd(&g_cnt[h], 1);
        }
    }
}

// ---------------- fused trunk, K64 chunks, 12 warps; scatter at tail ----------------
struct Frag { float c[2][4][4]; };

__device__ __forceinline__ void compute_part(uint32_t abase, uint32_t bbase,
                                             Frag& f, int wm, int wn, int lane,
                                             int g0, int g1)
{
    const int arow = ((lane >> 3) & 1) * 8 + (lane & 7);
    const int ak   = (lane >> 4) * 8;
    const int bn   = ((lane >> 4) & 1) * 8 + (lane & 7);
    const int bk   = ((lane >> 3) & 1) * 8;
    #pragma unroll
    for (int g = g0; g <= g1; g++) {
        uint32_t a[2][4], b[2][4];
        #pragma unroll
        for (int mt = 0; mt < 2; mt++)
            ldsm4(a[mt], abase + (uint32_t)(((wm * 32 + mt * 16 + arow) * PA + g * 16 + ak) * 2));
        #pragma unroll
        for (int p = 0; p < 2; p++)
            ldsm4(b[p], bbase + (uint32_t)(((wn * 32 + p * 16 + bn) * PA + g * 16 + bk) * 2));
        #pragma unroll
        for (int mt = 0; mt < 2; mt++)
            #pragma unroll
            for (int nt = 0; nt < 4; nt++)
                mma16(f.c[mt][nt], a[mt][0], a[mt][1], a[mt][2], a[mt][3],
                      b[nt >> 1][(nt & 1) * 2], b[nt >> 1][(nt & 1) * 2 + 1]);
    }
}

// smem layout (bytes): A0 @0 (9216), A1 @9216, B0 @18432 (27648), B1 @46080,
//                      H blocks @73728 (3 x 9216) -> total 101376 (2 CTAs/SM)
#define SM_A(b)  ((b) * 9216)
#define SM_B(b)  (18432 + (b) * 27648)
#define SM_H(c)  (73728 + (c) * 9216)
#define FUSED_SMEM 101376

__global__ void __launch_bounds__(THR, 2) trunk_kernel(
    const float* __restrict__ x, const float* __restrict__ b1, const float* __restrict__ b2,
    const int* __restrict__ qid, const int* __restrict__ cor)
{
    extern __shared__ char sm[];
    const uint32_t sb = (uint32_t)__cvta_generic_to_shared(sm);
    const int tid  = threadIdx.x;
    const int lane = tid & 31;
    const int wid  = tid >> 5;
    const int wm   = wid & 1, wn = wid >> 1;     // wn 0..5
    const int row0 = blockIdx.x * 64;
    const int myk   = tid & 63;
    const int rbase = tid >> 6;

    Frag f;
    #pragma unroll
    for (int mt = 0; mt < 2; mt++)
        #pragma unroll
        for (int nt = 0; nt < 4; nt++)
            #pragma unroll
            for (int q = 0; q < 4; q++) f.c[mt][nt][q] = 0.f;

    // ================= phase 1: h = relu(x @ W1 + b1) =================
    {
        #pragma unroll
        for (int t = 0; t < 4; t++) {
            const int i = tid + t * THR, n = i >> 3, j = i & 7;
            CP16(sb + SM_B(0) + (uint32_t)(n * 144 + j * 16),
                 g_W1h + n * KPAD1 + j * 8);
        }
        CP_COMMIT();
    }
    {
        __half* Ah = (__half*)(sm + SM_A(0));
        const bool kv = (myk < D_INPUT);
        #pragma unroll
        for (int t = 0; t < 11; t++) {
            const int r = rbase + t * 6;
            if (r < 64) {
                float v = kv ? __ldg(&x[(size_t)(row0 + r) * D_INPUT + myk]) : 0.f;
                Ah[r * PA + myk] = __float2half_rn(v);
            }
        }
    }
    CP_WAIT0();
    __syncthreads();

    for (int c = 0; c < NCH1; c++) {
        const int nx = c + 1;
        float xa[6];
        const int k = nx * 64 + myk;
        const bool kv = (k < D_INPUT);
        if (nx < NCH1) {
            const uint32_t bdst = sb + SM_B(nx & 1);
            #pragma unroll
            for (int t = 0; t < 4; t++) {
                const int i = tid + t * THR, n = i >> 3, j = i & 7;
                CP16(bdst + (uint32_t)(n * 144 + j * 16),
                     g_W1h + n * KPAD1 + nx * 64 + j * 8);
            }
            CP_COMMIT();
            #pragma unroll
            for (int t = 0; t < 6; t++) {
                const int r = rbase + t * 6;
                xa[t] = kv ? __ldg(&x[(size_t)(row0 + r) * D_INPUT + k]) : 0.f;
            }
        }
        compute_part(sb + SM_A(c & 1), sb + SM_B(c & 1), f, wm, wn, lane, 0, 1);
        if (nx < NCH1) {
            __half* Ad = (__half*)(sm + SM_A(nx & 1));
            #pragma unroll
            for (int t = 0; t < 6; t++) {
                const int r = rbase + t * 6;
                Ad[r * PA + myk] = __float2half_rn(xa[t]);
            }
            #pragma unroll
            for (int t = 0; t < 5; t++) {
                const int r = rbase + (t + 6) * 6;
                xa[t] = (kv && r < 64) ? __ldg(&x[(size_t)(row0 + r) * D_INPUT + k]) : 0.f;
            }
        }
        compute_part(sb + SM_A(c & 1), sb + SM_B(c & 1), f, wm, wn, lane, 2, 3);
        if (nx < NCH1) {
            __half* Ad = (__half*)(sm + SM_A(nx & 1));
            #pragma unroll
            for (int t = 0; t < 5; t++) {
                const int r = rbase + (t + 6) * 6;
                if (r < 64) Ad[r * PA + myk] = __float2half_rn(xa[t]);
            }
            CP_WAIT0();
        }
        __syncthreads();
    }

    // ---- prefetch W2 chunk 0 into B0 (overlaps epilogue 1) ----
    {
        #pragma unroll
        for (int t = 0; t < 4; t++) {
            const int i = tid + t * THR, n = i >> 3, j = i & 7;
            CP16(sb + SM_B(0) + (uint32_t)(n * 144 + j * 16),
                 g_W2h + n * D_H + j * 8);
        }
        CP_COMMIT();
    }

    // ---- epilogue 1: H blocks = fp16(relu(c + b1)) in smem ----
    #pragma unroll
    for (int mt = 0; mt < 2; mt++) {
        const int r = wm * 32 + mt * 16 + (lane >> 2);
        #pragma unroll
        for (int nt = 0; nt < 4; nt++) {
            const int n = wn * 32 + nt * 8 + 2 * (lane & 3);
            const float bb0 = __ldg(&b1[n]), bb1 = __ldg(&b1[n + 1]);
            __half2 v0 = __floats2half2_rn(fmaxf(f.c[mt][nt][0] + bb0, 0.f),
                                           fmaxf(f.c[mt][nt][1] + bb1, 0.f));
            __half2 v1 = __floats2half2_rn(fmaxf(f.c[mt][nt][2] + bb0, 0.f),
                                           fmaxf(f.c[mt][nt][3] + bb1, 0.f));
            const uint32_t off = (uint32_t)(SM_H(n >> 6) + (r * PA + (n & 63)) * 2);
            *(uint32_t*)(sm + off)            = *(uint32_t*)&v0;
            *(uint32_t*)(sm + off + PA * 16)  = *(uint32_t*)&v1;
        }
    }

    #pragma unroll
    for (int mt = 0; mt < 2; mt++)
        #pragma unroll
        for (int nt = 0; nt < 4; nt++)
            #pragma unroll
            for (int q = 0; q < 4; q++) f.c[mt][nt][q] = 0.f;

    CP_WAIT0();
    __syncthreads();

    // ================= phase 2: feat = relu(H @ W2 + b2) =================
    for (int c = 0; c < NCH2; c++) {
        const int nx = c + 1;
        if (nx < NCH2) {
            const uint32_t bdst = sb + SM_B(nx & 1);
            #pragma unroll
            for (int t = 0; t < 4; t++) {
                const int i = tid + t * THR, n = i >> 3, j = i & 7;
                CP16(bdst + (uint32_t)(n * 144 + j * 16),
                     g_W2h + n * D_H + nx * 64 + j * 8);
            }
            CP_COMMIT();
        }
        compute_part(sb + SM_H(c), sb + SM_B(c & 1), f, wm, wn, lane, 0, 3);
        if (nx < NCH2) CP_WAIT0();
        __syncthreads();
    }

    // ---- epilogue 2: g_feat16 = fp16(relu(c + b2)) ----
    #pragma unroll
    for (int mt = 0; mt < 2; mt++) {
        const int r = row0 + wm * 32 + mt * 16 + (lane >> 2);
        #pragma unroll
        for (int nt = 0; nt < 4; nt++) {
            const int n = wn * 32 + nt * 8 + 2 * (lane & 3);
            const float bb0 = __ldg(&b2[n]), bb1 = __ldg(&b2[n + 1]);
            __half2 v0 = __floats2half2_rn(fmaxf(f.c[mt][nt][0] + bb0, 0.f),
                                           fmaxf(f.c[mt][nt][1] + bb1, 0.f));
            __half2 v1 = __floats2half2_rn(fmaxf(f.c[mt][nt][2] + bb0, 0.f),
                                           fmaxf(f.c[mt][nt][3] + bb1, 0.f));
            g_feat16[(size_t)r * 96 + (n >> 1)]       = *(uint32_t*)&v0;
            g_feat16[(size_t)(r + 8) * 96 + (n >> 1)] = *(uint32_t*)&v1;
        }
    }

    // ---- tail scatter: this CTA's 64 samples (overlaps kernel drain) ----
    if (tid < 64) {
        const int b = row0 + tid;
        const int h = qid[b] + cor[b] * NQ;
        g_order[g_off[h] + g_rank[b]] = b;
    }
}

// ---------------- scan (self-resetting) ----------------
__global__ void scan_kernel() {
    __shared__ int s[2048];
    const int t = threadIdx.x;
    s[t]        = (t < NHEADS) ? g_cnt[t] : 0;
    s[t + 1024] = (t + 1024 < NHEADS) ? g_cnt[t + 1024] : 0;
    if (t < NHEADS) g_cnt[t] = 0;
    if (t + 1024 < NHEADS) g_cnt[t + 1024] = 0;
    __syncthreads();
    for (int d = 1; d < 2048; d <<= 1) {
        int v0 = s[t], v1 = s[t + 1024];
        int a0 = (t >= d) ? s[t - d] : 0;
        int a1 = (t + 1024 >= d) ? s[t + 1024 - d] : 0;
        __syncthreads();
        s[t] = v0 + a0;
        s[t + 1024] = v1 + a1;
        __syncthreads();
    }
    if (t < NHEADS)          { int e = (t == 0) ? 0 : s[t - 1]; g_off[t] = e; }
    if (t + 1024 < NHEADS)   { g_off[t + 1024] = s[t + 1023]; }
    if (t == 0) g_off[NHEADS] = s[NHEADS - 1];
}

// ---------------- routed heads: one WARP per group, 4 warps/CTA, double-buffered ------
#define HROW_B   400           // smem row stride bytes; conflict-free
#define H_TILE_B 6400          // 16 rows * 400 B
#define H_WARP_B (2 * H_TILE_B)
#define HEADS_SMEM (4 * H_WARP_B)   // 51200, 128-thread CTAs

__global__ void __launch_bounds__(128, 4) heads_kernel(
    const float* __restrict__ Wh, const float* __restrict__ bh, float* __restrict__ out)
{
    extern __shared__ char sm[];
    const int tid  = threadIdx.x;
    const int lane = tid & 31;
    const int wid  = tid >> 5;
    const int g    = blockIdx.x * 4 + wid;           // 500*4 = 2000 exactly
    const uint32_t wbase = (uint32_t)__cvta_generic_to_shared(sm) + (uint32_t)(wid * H_WARP_B);

    const int start = g_off[g], end = g_off[g + 1];
    if (start >= end) return;

    // ---- B fragments (weights, fp16) in registers ----
    uint32_t bw[48];
    {
        const int n_lo = lane >> 2, q2 = 2 * (lane & 3);
        #pragma unroll
        for (int kk = 0; kk < 12; kk++) {
            #pragma unroll
            for (int p = 0; p < 2; p++) {
                const float* src = Wh + ((size_t)g * NC + p * 8 + n_lo) * D_H + kk * 16 + q2;
                const float2 lo = *(const float2*)src;
                const float2 hi = *(const float2*)(src + 8);
                const __half2 l2 = __floats2half2_rn(lo.x, lo.y);
                const __half2 h2 = __floats2half2_rn(hi.x, hi.y);
                bw[kk * 4 + p * 2]     = *(const uint32_t*)&l2;
                bw[kk * 4 + p * 2 + 1] = *(const uint32_t*)&h2;
            }
        }
    }
    float bb[2][2];
    {
        const int col = 2 * (lane & 3);
        bb[0][0] = __ldg(&bh[g * NC + col]);
        bb[0][1] = __ldg(&bh[g * NC + col + 1]);
        bb[1][0] = __ldg(&bh[g * NC + 8 + col]);
        bb[1][1] = __ldg(&bh[g * NC + 8 + col + 1]);
    }

    const int myrow = lane & 15;
    const int seg0  = (lane >> 4) * 12;
    const int arow  = ((lane >> 3) & 1) * 8 + (lane & 7);
    const int ak2   = ((lane >> 4) * 8) * 2;
    const int r0    = lane >> 2, col = 2 * (lane & 3);

    const int nt_tiles = (end - start + 15) >> 4;

    // prologue: gather tile 0 into buf 0
    {
        const int sIdx = start + myrow;
        const int sC = (sIdx < end) ? sIdx : (end - 1);
        const char* src = (const char*)(g_feat16 + (size_t)g_order[sC] * 96);
        const uint32_t dst = wbase + (uint32_t)(myrow * HROW_B);
        #pragma unroll
        for (int t = 0; t < 12; t++) {
            const int j = seg0 + t;
            CP16(dst + (uint32_t)(j * 16), src + j * 16);
        }
        CP_COMMIT();
    }

    for (int ti = 0; ti < nt_tiles; ti++) {
        const int s0 = start + ti * 16;
        const bool more = (ti + 1 < nt_tiles);
        if (more) {      // prefetch tile ti+1 into the other buffer
            const int sIdx = s0 + 16 + myrow;
            const int sC = (sIdx < end) ? sIdx : (end - 1);
            const char* src = (const char*)(g_feat16 + (size_t)g_order[sC] * 96);
            const uint32_t dst = wbase + (uint32_t)(((ti + 1) & 1) * H_TILE_B + myrow * HROW_B);
            #pragma unroll
            for (int t = 0; t < 12; t++) {
                const int j = seg0 + t;
                CP16(dst + (uint32_t)(j * 16), src + j * 16);
            }
            CP_COMMIT();
            CP_WAIT1();  // tile ti complete; ti+1 still in flight
        } else {
            CP_WAIT0();
        }
        __syncwarp();

        const uint32_t tbase = wbase + (uint32_t)((ti & 1) * H_TILE_B);

        float acc[2][4];
        #pragma unroll
        for (int p = 0; p < 2; p++)
            #pragma unroll
            for (int q = 0; q < 4; q++) acc[p][q] = 0.f;

        #pragma unroll
        for (int kk = 0; kk < 12; kk++) {
            uint32_t a[4];
            ldsm4(a, tbase + (uint32_t)(arow * HROW_B + kk * 32) + (uint32_t)ak2);
            mma16(acc[0], a[0], a[1], a[2], a[3], bw[kk * 4],     bw[kk * 4 + 1]);
            mma16(acc[1], a[0], a[1], a[2], a[3], bw[kk * 4 + 2], bw[kk * 4 + 3]);
        }
        __syncwarp();    // all lanes done reading buf (ti) before it is re-gathered

        const int s_a = s0 + r0, s_b = s0 + r0 + 8;
        if (s_a < end) {
            float* o = out + (size_t)g_order[s_a] * NC;
            float2 v0 = { acc[0][0] + bb[0][0], acc[0][1] + bb[0][1] };
            float2 v1 = { acc[1][0] + bb[1][0], acc[1][1] + bb[1][1] };
            *(float2*)(o + col)     = v0;
            *(float2*)(o + 8 + col) = v1;
        }
        if (s_b < end) {
            float* o = out + (size_t)g_order[s_b] * NC;
            float2 v0 = { acc[0][2] + bb[0][0], acc[0][3] + bb[0][1] };
            float2 v1 = { acc[1][2] + bb[1][0], acc[1][3] + bb[1][1] };
            *(float2*)(o + col)     = v0;
            *(float2*)(o + 8 + col) = v1;
        }
    }
}

// ---------------- launch ----------------
extern "C" void kernel_launch(void* const* d_in, const int* in_sizes, int n_in,
                              void* d_out, int out_size) {
    const float* x   = (const float*)d_in[0];
    const int*   qid = (const int*)d_in[1];
    const int*   cor = (const int*)d_in[2];
    const float* W1  = (const float*)d_in[3];
    const float* b1  = (const float*)d_in[4];
    const float* W2  = (const float*)d_in[5];
    const float* b2  = (const float*)d_in[6];
    const float* Wh  = (const float*)d_in[7];
    const float* bh  = (const float*)d_in[8];
    float* out = (float*)d_out;

    cudaFuncSetAttribute(trunk_kernel, cudaFuncAttributeMaxDynamicSharedMemorySize, FUSED_SMEM);
    cudaFuncSetAttribute(heads_kernel, cudaFuncAttributeMaxDynamicSharedMemorySize, HEADS_SMEM);

    prep_hist_kernel<<<(PH_TOTAL + 255) / 256, 256>>>(W1, W2, qid, cor);
    scan_kernel<<<1, 1024>>>();
    trunk_kernel<<<B_TOTAL / 64, THR, FUSED_SMEM>>>(x, b1, b2, qid, cor);
    heads_kernel<<<NHEADS / 4, 128, HEADS_SMEM>>>(Wh, bh, out);
}

// round 17
// speedup vs baseline: 1.0102x; 1.0102x over previous
#include <cuda_runtime.h>
#include <cuda_fp16.h>
#include <cstdint>
#include <cstddef>

// ---------------- problem constants ----------------
#define B_TOTAL 131072
#define D_INPUT 385
#define D_H     192
#define NQ      1000
#define NHEADS  2000
#define NC      16

#define KPAD1   448            // 7 chunks of 64
#define NCH1    7
#define NCH2    3
#define PA      72             // smem pitch (halves); 144B row stride -> LDSM banks 4r, conflict-free
#define THR     384            // 12 warps

// ---------------- scratch (device globals: allocation-free) ----------------
__device__ uint32_t g_feat16[(size_t)B_TOTAL * 96];  // trunk output fp16, SORTED order, 50 MB
__device__ __half   g_W1h[D_H * KPAD1];              // W1^T fp16 [n][448], zero-padded
__device__ __half   g_W2h[D_H * D_H];                // W2^T fp16 [n][192]
__device__ int      g_cnt[NHEADS];                   // zero-init; scan re-zeroes each run
__device__ int      g_off[NHEADS + 1];
__device__ int      g_rank[B_TOTAL];
__device__ int      g_order[B_TOTAL];

// ---------------- PTX helpers ----------------
#define CP16(dst, src) \
    asm volatile("cp.async.cg.shared.global [%0], [%1], 16;" \
                 :: "r"(dst), "l"(__cvta_generic_to_global((const void*)(src))))
#define CP_COMMIT() asm volatile("cp.async.commit_group;" ::: "memory")
#define CP_WAIT0()  asm volatile("cp.async.wait_group 0;" ::: "memory")
#define CP_WAIT1()  asm volatile("cp.async.wait_group 1;" ::: "memory")

__device__ __forceinline__ void ldsm4(uint32_t r[4], uint32_t addr) {
    asm volatile("ldmatrix.sync.aligned.m8n8.x4.shared.b16 {%0,%1,%2,%3}, [%4];"
        : "=r"(r[0]), "=r"(r[1]), "=r"(r[2]), "=r"(r[3]) : "r"(addr));
}

__device__ __forceinline__ void mma16(float c[4], uint32_t a0, uint32_t a1,
                                      uint32_t a2, uint32_t a3, uint32_t b0, uint32_t b1) {
    asm volatile(
        "mma.sync.aligned.m16n8k16.row.col.f32.f16.f16.f32 "
        "{%0,%1,%2,%3}, {%4,%5,%6,%7}, {%8,%9}, {%0,%1,%2,%3};\n"
        : "+f"(c[0]), "+f"(c[1]), "+f"(c[2]), "+f"(c[3])
        : "r"(a0), "r"(a1), "r"(a2), "r"(a3), "r"(b0), "r"(b1));
}

// ---------------- prep + hist fused: weight conversion | histogram+rank ----------------
#define T1SZ (D_H * KPAD1)                 // 86016
#define T2SZ (D_H * D_H)                   // 36864
#define PH_TOTAL (T1SZ + T2SZ + B_TOTAL)   // 253952

__global__ void prep_hist_kernel(const float* __restrict__ W1, const float* __restrict__ W2,
                                 const int* __restrict__ qid, const int* __restrict__ cor) {
    int i = blockIdx.x * blockDim.x + threadIdx.x;
    if (i < T1SZ) {
        int n = i / KPAD1, k = i - n * KPAD1;
        float v = (k < D_INPUT) ? W1[(size_t)k * D_H + n] : 0.f;
        g_W1h[i] = __float2half_rn(v);
    } else if (i < T1SZ + T2SZ) {
        int j = i - T1SZ;
        int n = j / D_H, k = j - n * D_H;
        g_W2h[j] = __float2half_rn(W2[(size_t)k * D_H + n]);
    } else {
        int b = i - (T1SZ + T2SZ);
        if (b < B_TOTAL) {
            int h = qid[b] + cor[b] * NQ;
            g_rank[b] = atomicAdd(&g_cnt[h], 1);
        }
    }
}

// ---------------- fused trunk, K64 chunks, 12 warps; sorted feat stores ----------------
struct Frag { float c[2][4][4]; };

__device__ __forceinline__ void compute_part(uint32_t abase, uint32_t bbase,
                                             Frag& f, int wm, int wn, int lane,
                                             int g0, int g1)
{
    const int arow = ((lane >> 3) & 1) * 8 + (lane & 7);
    const int ak   = (lane >> 4) * 8;
    const int bn   = ((lane >> 4) & 1) * 8 + (lane & 7);
    const int bk   = ((lane >> 3) & 1) * 8;
    #pragma unroll
    for (int g = g0; g <= g1; g++) {
        uint32_t a[2][4], b[2][4];
        #pragma unroll
        for (int mt = 0; mt < 2; mt++)
            ldsm4(a[mt], abase + (uint32_t)(((wm * 32 + mt * 16 + arow) * PA + g * 16 + ak) * 2));
        #pragma unroll
        for (int p = 0; p < 2; p++)
            ldsm4(b[p], bbase + (uint32_t)(((wn * 32 + p * 16 + bn) * PA + g * 16 + bk) * 2));
        #pragma unroll
        for (int mt = 0; mt < 2; mt++)
            #pragma unroll
            for (int nt = 0; nt < 4; nt++)
                mma16(f.c[mt][nt], a[mt][0], a[mt][1], a[mt][2], a[mt][3],
                      b[nt >> 1][(nt & 1) * 2], b[nt >> 1][(nt & 1) * 2 + 1]);
    }
}

// smem layout (bytes): A0 @0 (9216), A1 @9216, B0 @18432 (27648), B1 @46080,
//                      H blocks @73728 (3 x 9216), pos @101376 (256)
#define SM_A(b)  ((b) * 9216)
#define SM_B(b)  (18432 + (b) * 27648)
#define SM_H(c)  (73728 + (c) * 9216)
#define SM_POS   101376
#define FUSED_SMEM 101632

__global__ void __launch_bounds__(THR, 2) trunk_kernel(
    const float* __restrict__ x, const float* __restrict__ b1, const float* __restrict__ b2,
    const int* __restrict__ qid, const int* __restrict__ cor)
{
    extern __shared__ char sm[];
    const uint32_t sb = (uint32_t)__cvta_generic_to_shared(sm);
    const int tid  = threadIdx.x;
    const int lane = tid & 31;
    const int wid  = tid >> 5;
    const int wm   = wid & 1, wn = wid >> 1;     // wn 0..5
    const int row0 = blockIdx.x * 64;
    const int myk   = tid & 63;
    const int rbase = tid >> 6;

    int* s_pos = (int*)(sm + SM_POS);

    Frag f;
    #pragma unroll
    for (int mt = 0; mt < 2; mt++)
        #pragma unroll
        for (int nt = 0; nt < 4; nt++)
            #pragma unroll
            for (int q = 0; q < 4; q++) f.c[mt][nt][q] = 0.f;

    // ================= phase 1: h = relu(x @ W1 + b1) =================
    {
        #pragma unroll
        for (int t = 0; t < 4; t++) {
            const int i = tid + t * THR, n = i >> 3, j = i & 7;
            CP16(sb + SM_B(0) + (uint32_t)(n * 144 + j * 16),
                 g_W1h + n * KPAD1 + j * 8);
        }
        CP_COMMIT();
    }
    {
        __half* Ah = (__half*)(sm + SM_A(0));
        const bool kv = (myk < D_INPUT);
        #pragma unroll
        for (int t = 0; t < 11; t++) {
            const int r = rbase + t * 6;
            if (r < 64) {
                float v = kv ? __ldg(&x[(size_t)(row0 + r) * D_INPUT + myk]) : 0.f;
                Ah[r * PA + myk] = __float2half_rn(v);
            }
        }
    }
    // ---- destination positions for this CTA's 64 samples (consumed in epilogue 2) ----
    int mypos = 0;
    if (tid < 64) {
        const int b = row0 + tid;
        const int h = qid[b] + cor[b] * NQ;
        mypos = g_off[h] + g_rank[b];
        s_pos[tid] = mypos;
    }
    CP_WAIT0();
    __syncthreads();

    for (int c = 0; c < NCH1; c++) {
        const int nx = c + 1;
        float xa[6];
        const int k = nx * 64 + myk;
        const bool kv = (k < D_INPUT);
        if (nx < NCH1) {
            const uint32_t bdst = sb + SM_B(nx & 1);
            #pragma unroll
            for (int t = 0; t < 4; t++) {
                const int i = tid + t * THR, n = i >> 3, j = i & 7;
                CP16(bdst + (uint32_t)(n * 144 + j * 16),
                     g_W1h + n * KPAD1 + nx * 64 + j * 8);
            }
            CP_COMMIT();
            #pragma unroll
            for (int t = 0; t < 6; t++) {
                const int r = rbase + t * 6;
                xa[t] = kv ? __ldg(&x[(size_t)(row0 + r) * D_INPUT + k]) : 0.f;
            }
        }
        compute_part(sb + SM_A(c & 1), sb + SM_B(c & 1), f, wm, wn, lane, 0, 1);
        if (nx < NCH1) {
            __half* Ad = (__half*)(sm + SM_A(nx & 1));
            #pragma unroll
            for (int t = 0; t < 6; t++) {
                const int r = rbase + t * 6;
                Ad[r * PA + myk] = __float2half_rn(xa[t]);
            }
            #pragma unroll
            for (int t = 0; t < 5; t++) {
                const int r = rbase + (t + 6) * 6;
                xa[t] = (kv && r < 64) ? __ldg(&x[(size_t)(row0 + r) * D_INPUT + k]) : 0.f;
            }
        }
        compute_part(sb + SM_A(c & 1), sb + SM_B(c & 1), f, wm, wn, lane, 2, 3);
        if (nx < NCH1) {
            __half* Ad = (__half*)(sm + SM_A(nx & 1));
            #pragma unroll
            for (int t = 0; t < 5; t++) {
                const int r = rbase + (t + 6) * 6;
                if (r < 64) Ad[r * PA + myk] = __float2half_rn(xa[t]);
            }
            CP_WAIT0();
        }
        __syncthreads();
    }

    // ---- prefetch W2 chunk 0 into B0 (overlaps epilogue 1) ----
    {
        #pragma unroll
        for (int t = 0; t < 4; t++) {
            const int i = tid + t * THR, n = i >> 3, j = i & 7;
            CP16(sb + SM_B(0) + (uint32_t)(n * 144 + j * 16),
                 g_W2h + n * D_H + j * 8);
        }
        CP_COMMIT();
    }

    // ---- epilogue 1: H blocks = fp16(relu(c + b1)) in smem ----
    #pragma unroll
    for (int mt = 0; mt < 2; mt++) {
        const int r = wm * 32 + mt * 16 + (lane >> 2);
        #pragma unroll
        for (int nt = 0; nt < 4; nt++) {
            const int n = wn * 32 + nt * 8 + 2 * (lane & 3);
            const float bb0 = __ldg(&b1[n]), bb1 = __ldg(&b1[n + 1]);
            __half2 v0 = __floats2half2_rn(fmaxf(f.c[mt][nt][0] + bb0, 0.f),
                                           fmaxf(f.c[mt][nt][1] + bb1, 0.f));
            __half2 v1 = __floats2half2_rn(fmaxf(f.c[mt][nt][2] + bb0, 0.f),
                                           fmaxf(f.c[mt][nt][3] + bb1, 0.f));
            const uint32_t off = (uint32_t)(SM_H(n >> 6) + (r * PA + (n & 63)) * 2);
            *(uint32_t*)(sm + off)            = *(uint32_t*)&v0;
            *(uint32_t*)(sm + off + PA * 16)  = *(uint32_t*)&v1;
        }
    }

    #pragma unroll
    for (int mt = 0; mt < 2; mt++)
        #pragma unroll
        for (int nt = 0; nt < 4; nt++)
            #pragma unroll
            for (int q = 0; q < 4; q++) f.c[mt][nt][q] = 0.f;

    CP_WAIT0();
    __syncthreads();

    // ================= phase 2: feat = relu(H @ W2 + b2) =================
    for (int c = 0; c < NCH2; c++) {
        const int nx = c + 1;
        if (nx < NCH2) {
            const uint32_t bdst = sb + SM_B(nx & 1);
            #pragma unroll
            for (int t = 0; t < 4; t++) {
                const int i = tid + t * THR, n = i >> 3, j = i & 7;
                CP16(bdst + (uint32_t)(n * 144 + j * 16),
                     g_W2h + n * D_H + nx * 64 + j * 8);
            }
            CP_COMMIT();
        }
        compute_part(sb + SM_H(c), sb + SM_B(c & 1), f, wm, wn, lane, 0, 3);
        if (nx < NCH2) CP_WAIT0();
        __syncthreads();
    }

    // ---- epilogue 2: g_feat16[pos] = fp16(relu(c + b2))  (sorted order) ----
    #pragma unroll
    for (int mt = 0; mt < 2; mt++) {
        const int lr = wm * 32 + mt * 16 + (lane >> 2);
        const int p0 = s_pos[lr], p1 = s_pos[lr + 8];
        #pragma unroll
        for (int nt = 0; nt < 4; nt++) {
            const int n = wn * 32 + nt * 8 + 2 * (lane & 3);
            const float bb0 = __ldg(&b2[n]), bb1 = __ldg(&b2[n + 1]);
            __half2 v0 = __floats2half2_rn(fmaxf(f.c[mt][nt][0] + bb0, 0.f),
                                           fmaxf(f.c[mt][nt][1] + bb1, 0.f));
            __half2 v1 = __floats2half2_rn(fmaxf(f.c[mt][nt][2] + bb0, 0.f),
                                           fmaxf(f.c[mt][nt][3] + bb1, 0.f));
            g_feat16[(size_t)p0 * 96 + (n >> 1)] = *(uint32_t*)&v0;
            g_feat16[(size_t)p1 * 96 + (n >> 1)] = *(uint32_t*)&v1;
        }
    }

    // ---- tail: publish sorted->original mapping (for heads' out stores) ----
    if (tid < 64) g_order[mypos] = row0 + tid;
}

// ---------------- scan (self-resetting) ----------------
__global__ void scan_kernel() {
    __shared__ int s[2048];
    const int t = threadIdx.x;
    s[t]        = (t < NHEADS) ? g_cnt[t] : 0;
    s[t + 1024] = (t + 1024 < NHEADS) ? g_cnt[t + 1024] : 0;
    if (t < NHEADS) g_cnt[t] = 0;
    if (t + 1024 < NHEADS) g_cnt[t + 1024] = 0;
    __syncthreads();
    for (int d = 1; d < 2048; d <<= 1) {
        int v0 = s[t], v1 = s[t + 1024];
        int a0 = (t >= d) ? s[t - d] : 0;
        int a1 = (t + 1024 >= d) ? s[t + 1024 - d] : 0;
        __syncthreads();
        s[t] = v0 + a0;
        s[t + 1024] = v1 + a1;
        __syncthreads();
    }
    if (t < NHEADS)          { int e = (t == 0) ? 0 : s[t - 1]; g_off[t] = e; }
    if (t + 1024 < NHEADS)   { g_off[t + 1024] = s[t + 1023]; }
    if (t == 0) g_off[NHEADS] = s[NHEADS - 1];
}

// ---------------- routed heads: contiguous feat stream, double-buffered ----------------
#define HROW_B   400           // smem row stride bytes; conflict-free
#define H_TILE_B 6400          // 16 rows * 400 B
#define H_WARP_B (2 * H_TILE_B)
#define HEADS_SMEM (8 * H_WARP_B)   // 102400, 256-thread CTAs, 2 CTAs/SM

__global__ void __launch_bounds__(256, 2) heads_kernel(
    const float* __restrict__ Wh, const float* __restrict__ bh, float* __restrict__ out)
{
    extern __shared__ char sm[];
    const int tid  = threadIdx.x;
    const int lane = tid & 31;
    const int wid  = tid >> 5;
    const int g    = blockIdx.x * 8 + wid;           // 250*8 = 2000
    const uint32_t wbase = (uint32_t)__cvta_generic_to_shared(sm) + (uint32_t)(wid * H_WARP_B);

    const int start = g_off[g], end = g_off[g + 1];
    if (start >= end) return;

    // ---- B fragments (weights, fp16) in registers ----
    uint32_t bw[48];
    {
        const int n_lo = lane >> 2, q2 = 2 * (lane & 3);
        #pragma unroll
        for (int kk = 0; kk < 12; kk++) {
            #pragma unroll
            for (int p = 0; p < 2; p++) {
                const float* src = Wh + ((size_t)g * NC + p * 8 + n_lo) * D_H + kk * 16 + q2;
                const float2 lo = *(const float2*)src;
                const float2 hi = *(const float2*)(src + 8);
                const __half2 l2 = __floats2half2_rn(lo.x, lo.y);
                const __half2 h2 = __floats2half2_rn(hi.x, hi.y);
                bw[kk * 4 + p * 2]     = *(const uint32_t*)&l2;
                bw[kk * 4 + p * 2 + 1] = *(const uint32_t*)&h2;
            }
        }
    }
    float bb[2][2];
    {
        const int col = 2 * (lane & 3);
        bb[0][0] = __ldg(&bh[g * NC + col]);
        bb[0][1] = __ldg(&bh[g * NC + col + 1]);
        bb[1][0] = __ldg(&bh[g * NC + 8 + col]);
        bb[1][1] = __ldg(&bh[g * NC + 8 + col + 1]);
    }

    const int myrow = lane & 15;
    const int seg0  = (lane >> 4) * 12;
    const int arow  = ((lane >> 3) & 1) * 8 + (lane & 7);
    const int ak2   = ((lane >> 4) * 8) * 2;
    const int r0    = lane >> 2, col = 2 * (lane & 3);

    const int nt_tiles = (end - start + 15) >> 4;

    // prologue: stream tile 0 (contiguous rows) into buf 0
    {
        const int sC = min(start + myrow, end - 1);
        const char* src = (const char*)(g_feat16 + (size_t)sC * 96);
        const uint32_t dst = wbase + (uint32_t)(myrow * HROW_B);
        #pragma unroll
        for (int t = 0; t < 12; t++) {
            const int j = seg0 + t;
            CP16(dst + (uint32_t)(j * 16), src + j * 16);
        }
        CP_COMMIT();
    }

    for (int ti = 0; ti < nt_tiles; ti++) {
        const int s0 = start + ti * 16;
        const bool more = (ti + 1 < nt_tiles);

        // early out-index loads (latency hidden under wait + MMA)
        const int s_a = s0 + r0, s_b = s0 + r0 + 8;
        int ord_a = 0, ord_b = 0;
        if (s_a < end) ord_a = __ldg(&g_order[s_a]);
        if (s_b < end) ord_b = __ldg(&g_order[s_b]);

        if (more) {      // prefetch tile ti+1 (pure address arithmetic, no index dep)
            const int sC = min(s0 + 16 + myrow, end - 1);
            const char* src = (const char*)(g_feat16 + (size_t)sC * 96);
            const uint32_t dst = wbase + (uint32_t)(((ti + 1) & 1) * H_TILE_B + myrow * HROW_B);
            #pragma unroll
            for (int t = 0; t < 12; t++) {
                const int j = seg0 + t;
                CP16(dst + (uint32_t)(j * 16), src + j * 16);
            }
            CP_COMMIT();
            CP_WAIT1();
        } else {
            CP_WAIT0();
        }
        __syncwarp();

        const uint32_t tbase = wbase + (uint32_t)((ti & 1) * H_TILE_B);

        float acc[2][4];
        #pragma unroll
        for (int p = 0; p < 2; p++)
            #pragma unroll
            for (int q = 0; q < 4; q++) acc[p][q] = 0.f;

        #pragma unroll
        for (int kk = 0; kk < 12; kk++) {
            uint32_t a[4];
            ldsm4(a, tbase + (uint32_t)(arow * HROW_B + kk * 32) + (uint32_t)ak2);
            mma16(acc[0], a[0], a[1], a[2], a[3], bw[kk * 4],     bw[kk * 4 + 1]);
            mma16(acc[1], a[0], a[1], a[2], a[3], bw[kk * 4 + 2], bw[kk * 4 + 3]);
        }
        __syncwarp();    // all lanes done reading buf (ti) before it is re-streamed

        if (s_a < end) {
            float* o = out + (size_t)ord_a * NC;
            float2 v0 = { acc[0][0] + bb[0][0], acc[0][1] + bb[0][1] };
            float2 v1 = { acc[1][0] + bb[1][0], acc[1][1] + bb[1][1] };
            *(float2*)(o + col)     = v0;
            *(float2*)(o + 8 + col) = v1;
        }
        if (s_b < end) {
            float* o = out + (size_t)ord_b * NC;
            float2 v0 = { acc[0][2] + bb[0][0], acc[0][3] + bb[0][1] };
            float2 v1 = { acc[1][2] + bb[1][0], acc[1][3] + bb[1][1] };
            *(float2*)(o + col)     = v0;
            *(float2*)(o + 8 + col) = v1;
        }
    }
}

// ---------------- launch ----------------
extern "C" void kernel_launch(void* const* d_in, const int* in_sizes, int n_in,
                              void* d_out, int out_size) {
    const float* x   = (const float*)d_in[0];
    const int*   qid = (const int*)d_in[1];
    const int*   cor = (const int*)d_in[2];
    const float* W1  = (const float*)d_in[3];
    const float* b1  = (const float*)d_in[4];
    const float* W2  = (const float*)d_in[5];
    const float* b2  = (const float*)d_in[6];
    const float* Wh  = (const float*)d_in[7];
    const float* bh  = (const float*)d_in[8];
    float* out = (float*)d_out;

    cudaFuncSetAttribute(trunk_kernel, cudaFuncAttributeMaxDynamicSharedMemorySize, FUSED_SMEM);
    cudaFuncSetAttribute(heads_kernel, cudaFuncAttributeMaxDynamicSharedMemorySize, HEADS_SMEM);

    prep_hist_kernel<<<(PH_TOTAL + 255) / 256, 256>>>(W1, W2, qid, cor);
    scan_kernel<<<1, 1024>>>();
    trunk_kernel<<<B_TOTAL / 64, THR, FUSED_SMEM>>>(x, b1, b2, qid, cor);
    heads_kernel<<<NHEADS / 8, 256, HEADS_SMEM>>>(Wh, bh, out);
}